// round 6
// baseline (speedup 1.0000x reference)
#include <cuda_runtime.h>
#include <cuda_fp16.h>
#include <cstdint>

#define NODES 50000
#define F 64
#define E_MAX 2000000
#define SBS 512
#define SNB ((NODES + SBS - 1) / SBS)   // 98

// ---------------- scratch (device globals; no allocations allowed) ----------
__device__ float4 g_h4[NODES * (F / 4)];     // [NODES,64] layer-1 output (fp32)
__device__ __half g_xh[NODES * F];           // fp16 copy of x   (gather feed)
__device__ __half g_hh[NODES * F];           // fp16 copy of h   (gather feed)
__device__ int    g_is32;                    // 1 if edge indices are int32

__device__ int g_cnt0[NODES], g_cnt1[NODES];
__device__ int g_rowptr0[NODES + 1], g_rowptr1[NODES + 1];
__device__ int g_cursor0[NODES], g_cursor1[NODES];
__device__ int g_csr0[E_MAX], g_csr1[E_MAX];

// decoupled-lookback scan state (reset by prep each replay)
__device__ unsigned long long g_tail[2 * SNB];   // (status<<62)|value
__device__ unsigned int g_ticket;

// ---------------- f32x2 packed-FMA helpers (FFMA2, sm_100+) ------------------
__device__ __forceinline__ unsigned long long pk2(float a) {
    unsigned long long r;
    asm("mov.b64 %0, {%1, %1};" : "=l"(r) : "f"(a));
    return r;
}
__device__ __forceinline__ void fma2(unsigned long long& d,
                                     unsigned long long a,
                                     unsigned long long b) {
    asm("fma.rn.f32x2 %0, %1, %2, %0;" : "+l"(d) : "l"(a), "l"(b));
}
__device__ __forceinline__ float2 up2(unsigned long long v) {
    float2 f;
    asm("mov.b64 {%0, %1}, %2;" : "=f"(f.x), "=f"(f.y) : "l"(v));
    return f;
}

// ---------------- prep: sniff + zero counts/scan-state + x->fp16 -------------
__global__ void prep_kernel(const long long* __restrict__ e0,
                            const float* __restrict__ x) {
    int i = blockIdx.x * blockDim.x + threadIdx.x;
    if (blockIdx.x == 0) {
        long long v = e0[threadIdx.x];
        int bad = (v < 0 || v >= (long long)NODES) ? 1 : 0;
        bad = __syncthreads_or(bad);
        if (threadIdx.x == 0) g_is32 = bad;
    }
    if (i < NODES) { g_cnt0[i] = 0; g_cnt1[i] = 0; }
    if (i < 2 * SNB) g_tail[i] = 0ull;
    if (i == 0) g_ticket = 0u;
    if (i < NODES * (F / 4)) {
        float4 v = ((const float4*)x)[i];
        union { __half2 h[2]; uint2 u; } cv;
        cv.h[0] = __floats2half2_rn(v.x, v.y);
        cv.h[1] = __floats2half2_rn(v.z, v.w);
        ((uint2*)g_xh)[i] = cv.u;
    }
}

// ---------------- count both layers: 4 edges x 2 lists per thread -----------
__global__ void count_both_kernel(const void* __restrict__ e0,
                                  const void* __restrict__ e1, int E) {
    int t = blockIdx.x * blockDim.x + threadIdx.x;
    int base = t * 4;
    if (base >= E) return;
    int c0[4], c1[4];
    if (base + 4 <= E) {
        if (g_is32) {
            int4 a = __ldg((const int4*)((const int*)e0 + E) + t);
            int4 b = __ldg((const int4*)((const int*)e1 + E) + t);
            c0[0] = a.x; c0[1] = a.y; c0[2] = a.z; c0[3] = a.w;
            c1[0] = b.x; c1[1] = b.y; c1[2] = b.z; c1[3] = b.w;
        } else {
            const long long* p0 = (const long long*)e0 + E;
            const long long* p1 = (const long long*)e1 + E;
            longlong2 a0 = __ldg((const longlong2*)p0 + 2 * t);
            longlong2 a1 = __ldg((const longlong2*)p0 + 2 * t + 1);
            longlong2 b0 = __ldg((const longlong2*)p1 + 2 * t);
            longlong2 b1 = __ldg((const longlong2*)p1 + 2 * t + 1);
            c0[0] = (int)a0.x; c0[1] = (int)a0.y; c0[2] = (int)a1.x; c0[3] = (int)a1.y;
            c1[0] = (int)b0.x; c1[1] = (int)b0.y; c1[2] = (int)b1.x; c1[3] = (int)b1.y;
        }
#pragma unroll
        for (int k = 0; k < 4; k++) {
            atomicAdd(&g_cnt0[c0[k]], 1);
            atomicAdd(&g_cnt1[c1[k]], 1);
        }
    } else {
        for (int k = 0; k < E - base; k++) {
            int a, b;
            if (g_is32) {
                a = __ldg((const int*)e0 + E + base + k);
                b = __ldg((const int*)e1 + E + base + k);
            } else {
                a = (int)__ldg((const long long*)e0 + E + base + k);
                b = (int)__ldg((const long long*)e1 + E + base + k);
            }
            atomicAdd(&g_cnt0[a], 1);
            atomicAdd(&g_cnt1[b], 1);
        }
    }
}

// ---------------- single-pass scan (decoupled lookback), both layers --------
// grid = 2*SNB blocks; virtual block id via atomic ticket guarantees that
// within a set, predecessor tiles started earlier (deadlock-free lookback).
__global__ void __launch_bounds__(SBS) scan_both_kernel() {
    __shared__ int sh_bid;
    __shared__ int sh_total;
    __shared__ long long sh_pref;
    __shared__ int ws[SBS / 32];
    int tid = threadIdx.x;
    if (tid == 0) sh_bid = (int)atomicAdd(&g_ticket, 1u);
    __syncthreads();
    int vb = sh_bid;
    int set = vb & 1;
    int j = vb >> 1;
    const int* cnt = set ? g_cnt1 : g_cnt0;
    int* rowptr = set ? g_rowptr1 : g_rowptr0;
    int* cursor = set ? g_cursor1 : g_cursor0;
    unsigned long long* tail = g_tail + set * SNB;

    int i = j * SBS + tid;
    int v = (i < NODES) ? cnt[i] : 0;
    int lane = tid & 31, warp = tid >> 5;
    int x = v;
#pragma unroll
    for (int o = 1; o < 32; o <<= 1) {
        int y = __shfl_up_sync(0xFFFFFFFFu, x, o);
        if (lane >= o) x += y;
    }
    if (lane == 31) ws[warp] = x;
    __syncthreads();
    if (warp == 0) {
        int s = (lane < SBS / 32) ? ws[lane] : 0;
#pragma unroll
        for (int o = 1; o < 32; o <<= 1) {
            int y = __shfl_up_sync(0xFFFFFFFFu, s, o);
            if (lane >= o) s += y;
        }
        if (lane < SBS / 32) ws[lane] = s;
    }
    __syncthreads();
    if (warp > 0) x += ws[warp - 1];
    if (tid == SBS - 1) sh_total = x;
    __syncthreads();
    int total = sh_total;

    if (tid == 0) {
        if (j == 0) {
            atomicExch(&tail[0], (2ull << 62) | (unsigned long long)total);
            sh_pref = 0;
        } else {
            atomicExch(&tail[j], (1ull << 62) | (unsigned long long)total);
            long long p = 0;
            int k = j - 1;
            while (true) {
                unsigned long long tv = atomicAdd(&tail[k], 0ull);
                unsigned st = (unsigned)(tv >> 62);
                if (st == 0) continue;        // not yet published; spin
                p += (long long)(tv & 0x3FFFFFFFFFFFFFFFull);
                if (st == 2) break;           // inclusive prefix reached
                --k;
            }
            atomicExch(&tail[j], (2ull << 62) | (unsigned long long)(p + total));
            sh_pref = p;
        }
    }
    __syncthreads();
    int pref = (int)sh_pref;
    if (i < NODES) {
        int incl = x + pref;
        rowptr[i + 1] = incl;
        cursor[i] = incl - v;
    }
    if (i == 0) rowptr[0] = 0;
}

// ---------------- place both layers ------------------------------------------
__global__ void place_both_kernel(const void* __restrict__ e0,
                                  const void* __restrict__ e1, int E) {
    int t = blockIdx.x * blockDim.x + threadIdx.x;
    int base = t * 4;
    if (base >= E) return;
    int r0[4], c0[4], r1[4], c1[4];
    if (base + 4 <= E) {
        if (g_is32) {
            int4 ra = __ldg((const int4*)e0 + t);
            int4 ca = __ldg((const int4*)((const int*)e0 + E) + t);
            int4 rb = __ldg((const int4*)e1 + t);
            int4 cb = __ldg((const int4*)((const int*)e1 + E) + t);
            r0[0] = ra.x; r0[1] = ra.y; r0[2] = ra.z; r0[3] = ra.w;
            c0[0] = ca.x; c0[1] = ca.y; c0[2] = ca.z; c0[3] = ca.w;
            r1[0] = rb.x; r1[1] = rb.y; r1[2] = rb.z; r1[3] = rb.w;
            c1[0] = cb.x; c1[1] = cb.y; c1[2] = cb.z; c1[3] = cb.w;
        } else {
            const long long* p0 = (const long long*)e0;
            const long long* p1 = (const long long*)e1;
            longlong2 ra0 = __ldg((const longlong2*)p0 + 2 * t);
            longlong2 ra1 = __ldg((const longlong2*)p0 + 2 * t + 1);
            longlong2 ca0 = __ldg((const longlong2*)(p0 + E) + 2 * t);
            longlong2 ca1 = __ldg((const longlong2*)(p0 + E) + 2 * t + 1);
            longlong2 rb0 = __ldg((const longlong2*)p1 + 2 * t);
            longlong2 rb1 = __ldg((const longlong2*)p1 + 2 * t + 1);
            longlong2 cb0 = __ldg((const longlong2*)(p1 + E) + 2 * t);
            longlong2 cb1 = __ldg((const longlong2*)(p1 + E) + 2 * t + 1);
            r0[0] = (int)ra0.x; r0[1] = (int)ra0.y; r0[2] = (int)ra1.x; r0[3] = (int)ra1.y;
            c0[0] = (int)ca0.x; c0[1] = (int)ca0.y; c0[2] = (int)ca1.x; c0[3] = (int)ca1.y;
            r1[0] = (int)rb0.x; r1[1] = (int)rb0.y; r1[2] = (int)rb1.x; r1[3] = (int)rb1.y;
            c1[0] = (int)cb0.x; c1[1] = (int)cb0.y; c1[2] = (int)cb1.x; c1[3] = (int)cb1.y;
        }
#pragma unroll
        for (int k = 0; k < 4; k++) {
            g_csr0[atomicAdd(&g_cursor0[c0[k]], 1)] = r0[k];
            g_csr1[atomicAdd(&g_cursor1[c1[k]], 1)] = r1[k];
        }
    } else {
        for (int k = 0; k < E - base; k++) {
            int rr0, cc0, rr1, cc1;
            if (g_is32) {
                rr0 = __ldg((const int*)e0 + base + k);
                cc0 = __ldg((const int*)e0 + E + base + k);
                rr1 = __ldg((const int*)e1 + base + k);
                cc1 = __ldg((const int*)e1 + E + base + k);
            } else {
                rr0 = (int)__ldg((const long long*)e0 + base + k);
                cc0 = (int)__ldg((const long long*)e0 + E + base + k);
                rr1 = (int)__ldg((const long long*)e1 + base + k);
                cc1 = (int)__ldg((const long long*)e1 + E + base + k);
            }
            g_csr0[atomicAdd(&g_cursor0[cc0], 1)] = rr0;
            g_csr1[atomicAdd(&g_cursor1[cc1], 1)] = rr1;
        }
    }
}

// ---------------- fused gather + dense ---------------------------------------
// Block = 128 nodes. Phase A: each warp gathers+means 16 nodes' fp16 neighbor
// rows directly into the k-major As tile. Phase B: FFMA2 mainloop vs W, then
// re-stage As from the fp32 root input and run vs R. Epilogue: bias+relu
// (+fp16 copy) or bias+L2norm.
template <bool RELU, bool NORM, int SET>
__global__ void __launch_bounds__(256) dense_fused_kernel(
    const float* __restrict__ xroot,
    const float* __restrict__ W, const float* __restrict__ bias,
    const float* __restrict__ R, float* __restrict__ out, int n_nodes) {
    extern __shared__ float smem[];
    float* As = smem;                    // [64][132]
    float* Ws = smem + F * 132;          // [64][64]
    float* sb = Ws + F * F;              // [64]

    const __half* srch = SET ? g_hh : g_xh;
    const int* rowptr = SET ? g_rowptr1 : g_rowptr0;
    const int* csr = SET ? g_csr1 : g_csr0;

    int tid = threadIdx.x;
    int lane = tid & 31, w = tid >> 5;
    int n0 = blockIdx.x * 128;

    if (tid < F) sb[tid] = bias[tid];

    // ---- phase A: gather into As (k-major), lane owns cols 2*lane, 2*lane+1
    for (int j = 0; j < 16; ++j) {
        int i = w * 16 + j;
        int n = n0 + i;
        int s = 0, e = 0;
        if (n < n_nodes) { s = __ldg(&rowptr[n]); e = __ldg(&rowptr[n + 1]); }
        float ax = 0.f, ay = 0.f;
        int it = s;
        for (; it + 8 <= e; it += 8) {
            int r[8];
#pragma unroll
            for (int k = 0; k < 8; k++) r[k] = __ldg(&csr[it + k]);
#pragma unroll
            for (int k = 0; k < 8; k++) {
                float2 v = __half22float2(
                    *((const __half2*)(srch + (size_t)r[k] * F) + lane));
                ax += v.x; ay += v.y;
            }
        }
        for (; it < e; ++it) {
            int r = __ldg(&csr[it]);
            float2 v = __half22float2(
                *((const __half2*)(srch + (size_t)r * F) + lane));
            ax += v.x; ay += v.y;
        }
        float inv = 1.f / (float)max(e - s, 1);
        As[(2 * lane) * 132 + i] = ax * inv;
        As[(2 * lane + 1) * 132 + i] = ay * inv;
    }
    // stage W
#pragma unroll
    for (int t = 0; t < 4; ++t) {
        int q = tid + 256 * t;
        *(float4*)(Ws + q * 4) = *(const float4*)(W + q * 4);
    }
    __syncthreads();

    unsigned long long acc2[8][2];
#pragma unroll
    for (int a = 0; a < 8; a++) { acc2[a][0] = 0ull; acc2[a][1] = 0ull; }

    int j0 = (tid & 15) * 4;
    int i0 = (tid >> 4) * 8;

    // ---- mainloop c=0 (agg vs W)
#pragma unroll
    for (int k = 0; k < F; ++k) {
        float4 a0 = *(const float4*)&As[k * 132 + i0];
        float4 a1 = *(const float4*)&As[k * 132 + i0 + 4];
        ulonglong2 wv = *(const ulonglong2*)&Ws[k * F + j0];
        unsigned long long p;
        p = pk2(a0.x); fma2(acc2[0][0], p, wv.x); fma2(acc2[0][1], p, wv.y);
        p = pk2(a0.y); fma2(acc2[1][0], p, wv.x); fma2(acc2[1][1], p, wv.y);
        p = pk2(a0.z); fma2(acc2[2][0], p, wv.x); fma2(acc2[2][1], p, wv.y);
        p = pk2(a0.w); fma2(acc2[3][0], p, wv.x); fma2(acc2[3][1], p, wv.y);
        p = pk2(a1.x); fma2(acc2[4][0], p, wv.x); fma2(acc2[4][1], p, wv.y);
        p = pk2(a1.y); fma2(acc2[5][0], p, wv.x); fma2(acc2[5][1], p, wv.y);
        p = pk2(a1.z); fma2(acc2[6][0], p, wv.x); fma2(acc2[6][1], p, wv.y);
        p = pk2(a1.w); fma2(acc2[7][0], p, wv.x); fma2(acc2[7][1], p, wv.y);
    }
    __syncthreads();

    // ---- re-stage: As from fp32 root input (transposed), Ws from R
#pragma unroll
    for (int t = 0; t < 8; ++t) {
        int q = tid + 256 * t;              // [0,2048)
        int i = q >> 4;
        int kk = (q & 15) << 2;
        int n = n0 + i;
        float4 v = make_float4(0.f, 0.f, 0.f, 0.f);
        if (n < n_nodes) v = *(const float4*)(xroot + (size_t)n * F + kk);
        As[(kk + 0) * 132 + i] = v.x;
        As[(kk + 1) * 132 + i] = v.y;
        As[(kk + 2) * 132 + i] = v.z;
        As[(kk + 3) * 132 + i] = v.w;
    }
#pragma unroll
    for (int t = 0; t < 4; ++t) {
        int q = tid + 256 * t;
        *(float4*)(Ws + q * 4) = *(const float4*)(R + q * 4);
    }
    __syncthreads();

    // ---- mainloop c=1 (root vs R)
#pragma unroll
    for (int k = 0; k < F; ++k) {
        float4 a0 = *(const float4*)&As[k * 132 + i0];
        float4 a1 = *(const float4*)&As[k * 132 + i0 + 4];
        ulonglong2 wv = *(const ulonglong2*)&Ws[k * F + j0];
        unsigned long long p;
        p = pk2(a0.x); fma2(acc2[0][0], p, wv.x); fma2(acc2[0][1], p, wv.y);
        p = pk2(a0.y); fma2(acc2[1][0], p, wv.x); fma2(acc2[1][1], p, wv.y);
        p = pk2(a0.z); fma2(acc2[2][0], p, wv.x); fma2(acc2[2][1], p, wv.y);
        p = pk2(a0.w); fma2(acc2[3][0], p, wv.x); fma2(acc2[3][1], p, wv.y);
        p = pk2(a1.x); fma2(acc2[4][0], p, wv.x); fma2(acc2[4][1], p, wv.y);
        p = pk2(a1.y); fma2(acc2[5][0], p, wv.x); fma2(acc2[5][1], p, wv.y);
        p = pk2(a1.z); fma2(acc2[6][0], p, wv.x); fma2(acc2[6][1], p, wv.y);
        p = pk2(a1.w); fma2(acc2[7][0], p, wv.x); fma2(acc2[7][1], p, wv.y);
    }

    // ---- epilogue
    float o[8][4];
#pragma unroll
    for (int ii = 0; ii < 8; ++ii) {
        float2 lo = up2(acc2[ii][0]);
        float2 hi = up2(acc2[ii][1]);
        o[ii][0] = lo.x + sb[j0 + 0];
        o[ii][1] = lo.y + sb[j0 + 1];
        o[ii][2] = hi.x + sb[j0 + 2];
        o[ii][3] = hi.y + sb[j0 + 3];
        if (RELU) {
            o[ii][0] = fmaxf(o[ii][0], 0.f); o[ii][1] = fmaxf(o[ii][1], 0.f);
            o[ii][2] = fmaxf(o[ii][2], 0.f); o[ii][3] = fmaxf(o[ii][3], 0.f);
        }
    }
    if (NORM) {
#pragma unroll
        for (int ii = 0; ii < 8; ++ii) {
            float ss = o[ii][0] * o[ii][0] + o[ii][1] * o[ii][1] +
                       o[ii][2] * o[ii][2] + o[ii][3] * o[ii][3];
#pragma unroll
            for (int m = 1; m < 16; m <<= 1)
                ss += __shfl_xor_sync(0xFFFFFFFFu, ss, m);
            float inv = 1.f / fmaxf(sqrtf(ss), 1e-12f);
            o[ii][0] *= inv; o[ii][1] *= inv;
            o[ii][2] *= inv; o[ii][3] *= inv;
        }
    }
#pragma unroll
    for (int ii = 0; ii < 8; ++ii) {
        int n = n0 + i0 + ii;
        if (n < n_nodes) {
            float4 v = make_float4(o[ii][0], o[ii][1], o[ii][2], o[ii][3]);
            *(float4*)(out + (size_t)n * F + j0) = v;
            if (RELU) {   // fp16 copy for the next gather
                union { __half2 h[2]; uint2 u; } cv;
                cv.h[0] = __floats2half2_rn(o[ii][0], o[ii][1]);
                cv.h[1] = __floats2half2_rn(o[ii][2], o[ii][3]);
                *(uint2*)(g_hh + (size_t)n * F + j0) = cv.u;
            }
        }
    }
}

// ---------------- launch -----------------------------------------------------
extern "C" void kernel_launch(void* const* d_in, const int* in_sizes, int n_in,
                              void* d_out, int out_size) {
    const float* x  = (const float*)d_in[0];
    const void*  e0 = d_in[1];
    const void*  e1 = d_in[2];
    const float* W1 = (const float*)d_in[3];
    const float* b1 = (const float*)d_in[4];
    const float* R1 = (const float*)d_in[5];
    const float* W2 = (const float*)d_in[6];
    const float* b2 = (const float*)d_in[7];
    const float* R2 = (const float*)d_in[8];
    float* out = (float*)d_out;

    static float* h4 = nullptr;
    if (!h4) {
        void* p;
        cudaGetSymbolAddress(&p, g_h4); h4 = (float*)p;
        cudaFuncSetAttribute(dense_fused_kernel<true, false, 0>,
                             cudaFuncAttributeMaxDynamicSharedMemorySize, 51200);
        cudaFuncSetAttribute(dense_fused_kernel<false, true, 1>,
                             cudaFuncAttributeMaxDynamicSharedMemorySize, 51200);
    }

    int E = in_sizes[1] / 2;
    int n_nodes = out_size / F;              // 50000
    int dsmem = (F * 132 + F * F + F) * 4;   // 50432 B

    int cb = ((E + 3) / 4 + 255) / 256;
    int pb = (NODES * F / 4 + 255) / 256;
    int db = (n_nodes + 127) / 128;

    prep_kernel<<<pb, 256>>>((const long long*)e0, x);
    count_both_kernel<<<cb, 256>>>(e0, e1, E);
    scan_both_kernel<<<2 * SNB, SBS>>>();
    place_both_kernel<<<cb, 256>>>(e0, e1, E);

    dense_fused_kernel<true, false, 0><<<db, 256, dsmem>>>(
        x, W1, b1, R1, h4, n_nodes);
    dense_fused_kernel<false, true, 1><<<db, 256, dsmem>>>(
        h4, W2, b2, R2, out, n_nodes);
}

// round 7
// speedup vs baseline: 1.1664x; 1.1664x over previous
#include <cuda_runtime.h>
#include <cuda_fp16.h>
#include <cstdint>

#define NODES 50000
#define F 64
#define E_MAX 2000000
#define SBS 512
#define SNB ((NODES + SBS - 1) / SBS)   // 98

// ---------------- scratch (device globals; no allocations allowed) ----------
__device__ float4 g_agg4[NODES * (F / 4)];   // [NODES,64] mean-aggregated feats
__device__ float4 g_h4[NODES * (F / 4)];     // [NODES,64] layer-1 output (fp32)
__device__ __half g_xh[NODES * F];           // fp16 copy of x   (gather feed)
__device__ __half g_hh[NODES * F];           // fp16 copy of h   (gather feed)
__device__ int    g_is32;                    // 1 if edge indices are int32

__device__ int g_cnt0[NODES], g_cnt1[NODES];
__device__ int g_rowptr0[NODES + 1], g_rowptr1[NODES + 1];
__device__ int g_rank0[E_MAX], g_rank1[E_MAX];   // intra-node edge ranks
__device__ int g_csr0[E_MAX], g_csr1[E_MAX];

// decoupled-lookback scan state (reset by prep each replay)
__device__ unsigned long long g_tail[2 * SNB];   // (status<<62)|value
__device__ unsigned int g_ticket;

// ---------------- f32x2 packed-FMA helpers (FFMA2, sm_100+) ------------------
__device__ __forceinline__ unsigned long long pk2(float a) {
    unsigned long long r;
    asm("mov.b64 %0, {%1, %1};" : "=l"(r) : "f"(a));
    return r;
}
__device__ __forceinline__ void fma2(unsigned long long& d,
                                     unsigned long long a,
                                     unsigned long long b) {
    asm("fma.rn.f32x2 %0, %1, %2, %0;" : "+l"(d) : "l"(a), "l"(b));
}
__device__ __forceinline__ float2 up2(unsigned long long v) {
    float2 f;
    asm("mov.b64 {%0, %1}, %2;" : "=f"(f.x), "=f"(f.y) : "l"(v));
    return f;
}

// ---------------- prep: sniff + zero counts/scan-state + x->fp16 -------------
__global__ void prep_kernel(const long long* __restrict__ e0,
                            const float* __restrict__ x) {
    int i = blockIdx.x * blockDim.x + threadIdx.x;
    if (blockIdx.x == 0) {
        long long v = e0[threadIdx.x];
        int bad = (v < 0 || v >= (long long)NODES) ? 1 : 0;
        bad = __syncthreads_or(bad);
        if (threadIdx.x == 0) g_is32 = bad;
    }
    if (i < NODES) { g_cnt0[i] = 0; g_cnt1[i] = 0; }
    if (i < 2 * SNB) g_tail[i] = 0ull;
    if (i == 0) g_ticket = 0u;
    if (i < NODES * (F / 4)) {
        float4 v = ((const float4*)x)[i];
        union { __half2 h[2]; uint2 u; } cv;
        cv.h[0] = __floats2half2_rn(v.x, v.y);
        cv.h[1] = __floats2half2_rn(v.z, v.w);
        ((uint2*)g_xh)[i] = cv.u;
    }
}

// ---------------- count both layers + record intra-node ranks ----------------
__global__ void count_both_kernel(const void* __restrict__ e0,
                                  const void* __restrict__ e1, int E) {
    int t = blockIdx.x * blockDim.x + threadIdx.x;
    int base = t * 4;
    if (base >= E) return;
    if (base + 4 <= E) {
        int c0[4], c1[4];
        if (g_is32) {
            int4 a = __ldg((const int4*)((const int*)e0 + E) + t);
            int4 b = __ldg((const int4*)((const int*)e1 + E) + t);
            c0[0] = a.x; c0[1] = a.y; c0[2] = a.z; c0[3] = a.w;
            c1[0] = b.x; c1[1] = b.y; c1[2] = b.z; c1[3] = b.w;
        } else {
            const long long* p0 = (const long long*)e0 + E;
            const long long* p1 = (const long long*)e1 + E;
            longlong2 a0 = __ldg((const longlong2*)p0 + 2 * t);
            longlong2 a1 = __ldg((const longlong2*)p0 + 2 * t + 1);
            longlong2 b0 = __ldg((const longlong2*)p1 + 2 * t);
            longlong2 b1 = __ldg((const longlong2*)p1 + 2 * t + 1);
            c0[0] = (int)a0.x; c0[1] = (int)a0.y; c0[2] = (int)a1.x; c0[3] = (int)a1.y;
            c1[0] = (int)b0.x; c1[1] = (int)b0.y; c1[2] = (int)b1.x; c1[3] = (int)b1.y;
        }
        int4 rk0, rk1;
        rk0.x = atomicAdd(&g_cnt0[c0[0]], 1);
        rk0.y = atomicAdd(&g_cnt0[c0[1]], 1);
        rk0.z = atomicAdd(&g_cnt0[c0[2]], 1);
        rk0.w = atomicAdd(&g_cnt0[c0[3]], 1);
        rk1.x = atomicAdd(&g_cnt1[c1[0]], 1);
        rk1.y = atomicAdd(&g_cnt1[c1[1]], 1);
        rk1.z = atomicAdd(&g_cnt1[c1[2]], 1);
        rk1.w = atomicAdd(&g_cnt1[c1[3]], 1);
        *((int4*)g_rank0 + t) = rk0;
        *((int4*)g_rank1 + t) = rk1;
    } else {
        for (int k = 0; k < E - base; k++) {
            int a, b;
            if (g_is32) {
                a = __ldg((const int*)e0 + E + base + k);
                b = __ldg((const int*)e1 + E + base + k);
            } else {
                a = (int)__ldg((const long long*)e0 + E + base + k);
                b = (int)__ldg((const long long*)e1 + E + base + k);
            }
            g_rank0[base + k] = atomicAdd(&g_cnt0[a], 1);
            g_rank1[base + k] = atomicAdd(&g_cnt1[b], 1);
        }
    }
}

// ---------------- single-pass scan (decoupled lookback), both layers --------
__global__ void __launch_bounds__(SBS) scan_both_kernel() {
    __shared__ int sh_bid;
    __shared__ int sh_total;
    __shared__ long long sh_pref;
    __shared__ int ws[SBS / 32];
    int tid = threadIdx.x;
    if (tid == 0) sh_bid = (int)atomicAdd(&g_ticket, 1u);
    __syncthreads();
    int vb = sh_bid;
    int set = vb & 1;
    int j = vb >> 1;
    const int* cnt = set ? g_cnt1 : g_cnt0;
    int* rowptr = set ? g_rowptr1 : g_rowptr0;
    unsigned long long* tail = g_tail + set * SNB;

    int i = j * SBS + tid;
    int v = (i < NODES) ? cnt[i] : 0;
    int lane = tid & 31, warp = tid >> 5;
    int x = v;
#pragma unroll
    for (int o = 1; o < 32; o <<= 1) {
        int y = __shfl_up_sync(0xFFFFFFFFu, x, o);
        if (lane >= o) x += y;
    }
    if (lane == 31) ws[warp] = x;
    __syncthreads();
    if (warp == 0) {
        int s = (lane < SBS / 32) ? ws[lane] : 0;
#pragma unroll
        for (int o = 1; o < 32; o <<= 1) {
            int y = __shfl_up_sync(0xFFFFFFFFu, s, o);
            if (lane >= o) s += y;
        }
        if (lane < SBS / 32) ws[lane] = s;
    }
    __syncthreads();
    if (warp > 0) x += ws[warp - 1];
    if (tid == SBS - 1) sh_total = x;
    __syncthreads();
    int total = sh_total;

    if (tid == 0) {
        if (j == 0) {
            atomicExch(&tail[0], (2ull << 62) | (unsigned long long)total);
            sh_pref = 0;
        } else {
            atomicExch(&tail[j], (1ull << 62) | (unsigned long long)total);
            long long p = 0;
            int k = j - 1;
            while (true) {
                unsigned long long tv = atomicAdd(&tail[k], 0ull);
                unsigned st = (unsigned)(tv >> 62);
                if (st == 0) continue;        // not yet published; spin
                p += (long long)(tv & 0x3FFFFFFFFFFFFFFFull);
                if (st == 2) break;           // inclusive prefix reached
                --k;
            }
            atomicExch(&tail[j], (2ull << 62) | (unsigned long long)(p + total));
            sh_pref = p;
        }
    }
    __syncthreads();
    int pref = (int)sh_pref;
    if (i < NODES) rowptr[i + 1] = x + pref;
    if (i == 0) rowptr[0] = 0;
}

// ---------------- place both layers (atomic-free, rank-based) ---------------
__global__ void place_both_kernel(const void* __restrict__ e0,
                                  const void* __restrict__ e1, int E) {
    int t = blockIdx.x * blockDim.x + threadIdx.x;
    int base = t * 4;
    if (base >= E) return;
    if (base + 4 <= E) {
        int r0[4], c0[4], r1[4], c1[4];
        if (g_is32) {
            int4 ra = __ldg((const int4*)e0 + t);
            int4 ca = __ldg((const int4*)((const int*)e0 + E) + t);
            int4 rb = __ldg((const int4*)e1 + t);
            int4 cb = __ldg((const int4*)((const int*)e1 + E) + t);
            r0[0] = ra.x; r0[1] = ra.y; r0[2] = ra.z; r0[3] = ra.w;
            c0[0] = ca.x; c0[1] = ca.y; c0[2] = ca.z; c0[3] = ca.w;
            r1[0] = rb.x; r1[1] = rb.y; r1[2] = rb.z; r1[3] = rb.w;
            c1[0] = cb.x; c1[1] = cb.y; c1[2] = cb.z; c1[3] = cb.w;
        } else {
            const long long* p0 = (const long long*)e0;
            const long long* p1 = (const long long*)e1;
            longlong2 ra0 = __ldg((const longlong2*)p0 + 2 * t);
            longlong2 ra1 = __ldg((const longlong2*)p0 + 2 * t + 1);
            longlong2 ca0 = __ldg((const longlong2*)(p0 + E) + 2 * t);
            longlong2 ca1 = __ldg((const longlong2*)(p0 + E) + 2 * t + 1);
            longlong2 rb0 = __ldg((const longlong2*)p1 + 2 * t);
            longlong2 rb1 = __ldg((const longlong2*)p1 + 2 * t + 1);
            longlong2 cb0 = __ldg((const longlong2*)(p1 + E) + 2 * t);
            longlong2 cb1 = __ldg((const longlong2*)(p1 + E) + 2 * t + 1);
            r0[0] = (int)ra0.x; r0[1] = (int)ra0.y; r0[2] = (int)ra1.x; r0[3] = (int)ra1.y;
            c0[0] = (int)ca0.x; c0[1] = (int)ca0.y; c0[2] = (int)ca1.x; c0[3] = (int)ca1.y;
            r1[0] = (int)rb0.x; r1[1] = (int)rb0.y; r1[2] = (int)rb1.x; r1[3] = (int)rb1.y;
            c1[0] = (int)cb0.x; c1[1] = (int)cb0.y; c1[2] = (int)cb1.x; c1[3] = (int)cb1.y;
        }
        int4 rk0 = *((const int4*)g_rank0 + t);
        int4 rk1 = *((const int4*)g_rank1 + t);
        int p00 = __ldg(&g_rowptr0[c0[0]]) + rk0.x;
        int p01 = __ldg(&g_rowptr0[c0[1]]) + rk0.y;
        int p02 = __ldg(&g_rowptr0[c0[2]]) + rk0.z;
        int p03 = __ldg(&g_rowptr0[c0[3]]) + rk0.w;
        int p10 = __ldg(&g_rowptr1[c1[0]]) + rk1.x;
        int p11 = __ldg(&g_rowptr1[c1[1]]) + rk1.y;
        int p12 = __ldg(&g_rowptr1[c1[2]]) + rk1.z;
        int p13 = __ldg(&g_rowptr1[c1[3]]) + rk1.w;
        g_csr0[p00] = r0[0]; g_csr0[p01] = r0[1];
        g_csr0[p02] = r0[2]; g_csr0[p03] = r0[3];
        g_csr1[p10] = r1[0]; g_csr1[p11] = r1[1];
        g_csr1[p12] = r1[2]; g_csr1[p13] = r1[3];
    } else {
        for (int k = 0; k < E - base; k++) {
            int rr0, cc0, rr1, cc1;
            if (g_is32) {
                rr0 = __ldg((const int*)e0 + base + k);
                cc0 = __ldg((const int*)e0 + E + base + k);
                rr1 = __ldg((const int*)e1 + base + k);
                cc1 = __ldg((const int*)e1 + E + base + k);
            } else {
                rr0 = (int)__ldg((const long long*)e0 + base + k);
                cc0 = (int)__ldg((const long long*)e0 + E + base + k);
                rr1 = (int)__ldg((const long long*)e1 + base + k);
                cc1 = (int)__ldg((const long long*)e1 + E + base + k);
            }
            g_csr0[__ldg(&g_rowptr0[cc0]) + g_rank0[base + k]] = rr0;
            g_csr1[__ldg(&g_rowptr1[cc1]) + g_rank1[base + k]] = rr1;
        }
    }
}

// ---------------- gather-side mean aggregation (fp16 feed, fp32 acc) --------
// one warp per node; each lane owns 2 columns (half2); unroll 8 for MLP
template <int SET>
__global__ void __launch_bounds__(256) gather_kernel(
    const __half* __restrict__ srch) {
    const int* rowptr = SET ? g_rowptr1 : g_rowptr0;
    const int* csr = SET ? g_csr1 : g_csr0;
    int tid = threadIdx.x;
    int node = blockIdx.x * 8 + (tid >> 5);
    if (node >= NODES) return;
    int lane = tid & 31;
    int s = __ldg(&rowptr[node]);
    int e = __ldg(&rowptr[node + 1]);
    float ax = 0.f, ay = 0.f;
    int i = s;
    for (; i + 8 <= e; i += 8) {
        int r[8];
#pragma unroll
        for (int k = 0; k < 8; k++) r[k] = __ldg(&csr[i + k]);
        float2 v[8];
#pragma unroll
        for (int k = 0; k < 8; k++)
            v[k] = __half22float2(*((const __half2*)(srch + (size_t)r[k] * F) + lane));
#pragma unroll
        for (int k = 0; k < 8; k++) { ax += v[k].x; ay += v[k].y; }
    }
    for (; i < e; i++) {
        int r = __ldg(&csr[i]);
        float2 v = __half22float2(*((const __half2*)(srch + (size_t)r * F) + lane));
        ax += v.x; ay += v.y;
    }
    float inv = 1.f / (float)max(e - s, 1);
    float2 o; o.x = ax * inv; o.y = ay * inv;
    *(float2*)((float*)g_agg4 + (size_t)node * F + lane * 2) = o;
}

// ---------------- fused dense: out = agg@W + b + xin@R ----------------------
// 128 nodes x 64 outputs, 256 threads, 8x4 blocking via packed FFMA2.
// RELU path additionally emits fp16 copy of the output into g_hh.
template <bool RELU, bool NORM>
__global__ void __launch_bounds__(256) dense_kernel(
    const float* __restrict__ xin,
    const float* __restrict__ W, const float* __restrict__ bias,
    const float* __restrict__ R, float* __restrict__ out, int n_nodes) {
    extern __shared__ float smem[];
    float* As = smem;                    // [64][132]
    float* Ws = smem + F * 132;          // [64][64]
    float* sb = Ws + F * F;              // [64]

    const float* agg = (const float*)g_agg4;
    int tid = threadIdx.x;
    int n0 = blockIdx.x * 128;

    if (tid < F) sb[tid] = bias[tid];

    unsigned long long acc2[8][2];
#pragma unroll
    for (int a = 0; a < 8; a++) { acc2[a][0] = 0ull; acc2[a][1] = 0ull; }

    int j0 = (tid & 15) * 4;
    int i0 = (tid >> 4) * 8;

#pragma unroll
    for (int c = 0; c < 2; ++c) {
        const float* src = c ? xin : agg;
        const float* wsrc = c ? R : W;
        __syncthreads();
#pragma unroll
        for (int t = 0; t < 8; ++t) {
            int q = tid + 256 * t;          // [0,2048)
            int i = q >> 4;                 // node within tile (0..127)
            int kk = (q & 15) << 2;         // k offset
            int n = n0 + i;
            float4 v = make_float4(0.f, 0.f, 0.f, 0.f);
            if (n < n_nodes) v = *(const float4*)(src + (size_t)n * F + kk);
            As[(kk + 0) * 132 + i] = v.x;
            As[(kk + 1) * 132 + i] = v.y;
            As[(kk + 2) * 132 + i] = v.z;
            As[(kk + 3) * 132 + i] = v.w;
        }
#pragma unroll
        for (int t = 0; t < 4; ++t) {
            int q = tid + 256 * t;          // [0,1024)
            *(float4*)(Ws + q * 4) = *(const float4*)(wsrc + q * 4);
        }
        __syncthreads();
#pragma unroll
        for (int k = 0; k < F; ++k) {
            float4 a0 = *(const float4*)&As[k * 132 + i0];
            float4 a1 = *(const float4*)&As[k * 132 + i0 + 4];
            ulonglong2 wv = *(const ulonglong2*)&Ws[k * F + j0];
            unsigned long long p;
            p = pk2(a0.x); fma2(acc2[0][0], p, wv.x); fma2(acc2[0][1], p, wv.y);
            p = pk2(a0.y); fma2(acc2[1][0], p, wv.x); fma2(acc2[1][1], p, wv.y);
            p = pk2(a0.z); fma2(acc2[2][0], p, wv.x); fma2(acc2[2][1], p, wv.y);
            p = pk2(a0.w); fma2(acc2[3][0], p, wv.x); fma2(acc2[3][1], p, wv.y);
            p = pk2(a1.x); fma2(acc2[4][0], p, wv.x); fma2(acc2[4][1], p, wv.y);
            p = pk2(a1.y); fma2(acc2[5][0], p, wv.x); fma2(acc2[5][1], p, wv.y);
            p = pk2(a1.z); fma2(acc2[6][0], p, wv.x); fma2(acc2[6][1], p, wv.y);
            p = pk2(a1.w); fma2(acc2[7][0], p, wv.x); fma2(acc2[7][1], p, wv.y);
        }
    }

    // epilogue
    float o[8][4];
#pragma unroll
    for (int ii = 0; ii < 8; ++ii) {
        float2 lo = up2(acc2[ii][0]);
        float2 hi = up2(acc2[ii][1]);
        o[ii][0] = lo.x + sb[j0 + 0];
        o[ii][1] = lo.y + sb[j0 + 1];
        o[ii][2] = hi.x + sb[j0 + 2];
        o[ii][3] = hi.y + sb[j0 + 3];
        if (RELU) {
            o[ii][0] = fmaxf(o[ii][0], 0.f); o[ii][1] = fmaxf(o[ii][1], 0.f);
            o[ii][2] = fmaxf(o[ii][2], 0.f); o[ii][3] = fmaxf(o[ii][3], 0.f);
        }
    }
    if (NORM) {
        // each row's 64 cols live in 16 lanes of one half-warp -> xor 1,2,4,8
#pragma unroll
        for (int ii = 0; ii < 8; ++ii) {
            float ss = o[ii][0] * o[ii][0] + o[ii][1] * o[ii][1] +
                       o[ii][2] * o[ii][2] + o[ii][3] * o[ii][3];
#pragma unroll
            for (int m = 1; m < 16; m <<= 1)
                ss += __shfl_xor_sync(0xFFFFFFFFu, ss, m);
            float inv = 1.f / fmaxf(sqrtf(ss), 1e-12f);
            o[ii][0] *= inv; o[ii][1] *= inv;
            o[ii][2] *= inv; o[ii][3] *= inv;
        }
    }
#pragma unroll
    for (int ii = 0; ii < 8; ++ii) {
        int n = n0 + i0 + ii;
        if (n < n_nodes) {
            float4 v = make_float4(o[ii][0], o[ii][1], o[ii][2], o[ii][3]);
            *(float4*)(out + (size_t)n * F + j0) = v;
            if (RELU) {   // fp16 copy for the next gather
                union { __half2 h[2]; uint2 u; } cv;
                cv.h[0] = __floats2half2_rn(o[ii][0], o[ii][1]);
                cv.h[1] = __floats2half2_rn(o[ii][2], o[ii][3]);
                *(uint2*)(g_hh + (size_t)n * F + j0) = cv.u;
            }
        }
    }
}

// ---------------- launch -----------------------------------------------------
extern "C" void kernel_launch(void* const* d_in, const int* in_sizes, int n_in,
                              void* d_out, int out_size) {
    const float* x  = (const float*)d_in[0];
    const void*  e0 = d_in[1];
    const void*  e1 = d_in[2];
    const float* W1 = (const float*)d_in[3];
    const float* b1 = (const float*)d_in[4];
    const float* R1 = (const float*)d_in[5];
    const float* W2 = (const float*)d_in[6];
    const float* b2 = (const float*)d_in[7];
    const float* R2 = (const float*)d_in[8];
    float* out = (float*)d_out;

    static float* h4 = nullptr;
    static __half* xh = nullptr;
    static __half* hh = nullptr;
    if (!h4) {
        void* p;
        cudaGetSymbolAddress(&p, g_h4); h4 = (float*)p;
        cudaGetSymbolAddress(&p, g_xh); xh = (__half*)p;
        cudaGetSymbolAddress(&p, g_hh); hh = (__half*)p;
        cudaFuncSetAttribute(dense_kernel<true, false>,
                             cudaFuncAttributeMaxDynamicSharedMemorySize, 51200);
        cudaFuncSetAttribute(dense_kernel<false, true>,
                             cudaFuncAttributeMaxDynamicSharedMemorySize, 51200);
    }

    int E = in_sizes[1] / 2;
    int n_nodes = out_size / F;              // 50000
    int dsmem = (F * 132 + F * F + F) * 4;   // 50432 B

    int cb = ((E + 3) / 4 + 255) / 256;
    int pb = (NODES * F / 4 + 255) / 256;
    int gb = (NODES + 7) / 8;
    int db = (n_nodes + 127) / 128;

    prep_kernel<<<pb, 256>>>((const long long*)e0, x);
    count_both_kernel<<<cb, 256>>>(e0, e1, E);
    scan_both_kernel<<<2 * SNB, SBS>>>();
    place_both_kernel<<<cb, 256>>>(e0, e1, E);

    // layer 1
    gather_kernel<0><<<gb, 256>>>(xh);
    dense_kernel<true, false><<<db, 256, dsmem>>>(x, W1, b1, R1, h4, n_nodes);

    // layer 2
    gather_kernel<1><<<gb, 256>>>(hh);
    dense_kernel<false, true><<<db, 256, dsmem>>>(h4, W2, b2, R2, out, n_nodes);
}